// round 7
// baseline (speedup 1.0000x reference)
#include <cuda_runtime.h>
#include <cuda_fp16.h>
#include <stdint.h>

#define MTOT  131072
#define KDIM  512
#define NQKV  1536
#define HEADS 16
#define DH    32
#define WIN   64
#define NB    2048

// ---------------- scratch (device globals; allocation-free) ----------------
__device__ __half g_xh[(size_t)MTOT * KDIM];        // x in fp16           128MB
__device__ __half g_wqkv_t[(size_t)NQKV * KDIM];    // w_qkv^T fp16        1.5MB
__device__ __half g_wproj_t[(size_t)KDIM * KDIM];   // w_proj^T fp16       0.5MB
__device__ __half g_qkv[(size_t)NB * HEADS * 3 * WIN * DH];  // q,k,v      384MB
__device__ __half g_attnout[(size_t)MTOT * KDIM];   // attention output    128MB

// ---------------- PTX helpers ----------------
__device__ __forceinline__ uint32_t smem_u32(const void* p) {
    uint32_t a;
    asm("{ .reg .u64 t; cvta.to.shared.u64 t, %1; cvt.u32.u64 %0, t; }" : "=r"(a) : "l"(p));
    return a;
}
__device__ __forceinline__ void cpasync16(uint32_t s, const void* g) {
    asm volatile("cp.async.cg.shared.global [%0], [%1], 16;\n" :: "r"(s), "l"(g));
}
__device__ __forceinline__ void ldsm_x4(uint32_t* r, const void* p) {
    uint32_t a = smem_u32(p);
    asm volatile("ldmatrix.sync.aligned.m8n8.x4.shared.b16 {%0,%1,%2,%3}, [%4];"
                 : "=r"(r[0]), "=r"(r[1]), "=r"(r[2]), "=r"(r[3]) : "r"(a));
}
__device__ __forceinline__ void ldsm_x4_t(uint32_t* r, const void* p) {
    uint32_t a = smem_u32(p);
    asm volatile("ldmatrix.sync.aligned.m8n8.x4.trans.shared.b16 {%0,%1,%2,%3}, [%4];"
                 : "=r"(r[0]), "=r"(r[1]), "=r"(r[2]), "=r"(r[3]) : "r"(a));
}
__device__ __forceinline__ void mma16816(float* c, const uint32_t* a, uint32_t b0, uint32_t b1) {
    asm volatile(
        "mma.sync.aligned.m16n8k16.row.col.f32.f16.f16.f32 "
        "{%0,%1,%2,%3},{%4,%5,%6,%7},{%8,%9},{%0,%1,%2,%3};"
        : "+f"(c[0]), "+f"(c[1]), "+f"(c[2]), "+f"(c[3])
        : "r"(a[0]), "r"(a[1]), "r"(a[2]), "r"(a[3]), "r"(b0), "r"(b1));
}
__device__ __forceinline__ uint32_t packh2(float a, float b) {
    __half2 h = __floats2half2_rn(a, b);
    return *(uint32_t*)&h;
}

// ---------------- converters ----------------
__global__ void conv_x_kernel(const float* __restrict__ x) {
    size_t i = (size_t)blockIdx.x * blockDim.x + threadIdx.x;
    float4 v = *(const float4*)(x + i * 4);
    __half2 a = __floats2half2_rn(v.x, v.y);
    __half2 b = __floats2half2_rn(v.z, v.w);
    uint2 o;
    o.x = *(uint32_t*)&a;
    o.y = *(uint32_t*)&b;
    *(uint2*)(g_xh + i * 4) = o;
}

__global__ void conv_w_kernel(const float* __restrict__ wqkv, const float* __restrict__ wproj) {
    int i = blockIdx.x * blockDim.x + threadIdx.x;
    if (i < NQKV * KDIM) {
        int n = i >> 9, k = i & 511;
        g_wqkv_t[i] = __float2half_rn(wqkv[(size_t)k * NQKV + n]);
    }
    if (i < KDIM * KDIM) {
        int n = i >> 9, k = i & 511;
        g_wproj_t[i] = __float2half_rn(wproj[(size_t)k * KDIM + n]);
    }
}

// ---------------- GEMM: C tile[128x128] = A[128x512] x Bt[128x512]^T ----------------
// 3-stage cp.async pipeline, BK=64, ONE __syncthreads per k-tile (8 total).
// grid: (Ntiles, Mtiles), bn fastest -> A-panel L2 reuse. 256 threads, 8 warps 64x32.
// smem: 3 stages x (A 128x72 + B 128x72) halves = 110592 B.
#define GEMM_SMEM_BYTES 110592
#define SSTRIDE 72

template <int MODE>   // 0 = qkv epilogue, 1 = proj epilogue
__global__ __launch_bounds__(256)
void gemm_hmma_kernel(const float* __restrict__ bias, float* __restrict__ outf) {
    extern __shared__ char smem_raw[];
    __half* sbase = (__half*)smem_raw;   // [3][2][128*72]  (A then B per stage)

    const int bn = blockIdx.x, bm = blockIdx.y;
    const int tid = threadIdx.x, lane = tid & 31, warp = tid >> 5;
    const int wm = warp >> 2, wn = warp & 3;

    const __half* A  = (MODE == 0) ? g_xh     : g_attnout;
    const __half* Bt = (MODE == 0) ? g_wqkv_t : g_wproj_t;
    const __half* gA = A  + (size_t)bm * 128 * KDIM;
    const __half* gB = Bt + (size_t)bn * 128 * KDIM;
    const float qscale = 0.17677669529663687f;   // 1/sqrt(32)

    // load tile t (K-chunk of 64) into stage buf
    auto load_tile = [&](int t, int buf) {
        __half* dA = sbase + buf * 2 * 128 * SSTRIDE;
        __half* dB = dA + 128 * SSTRIDE;
        #pragma unroll
        for (int c = 0; c < 8; ++c) {
            int idx = tid + c * 256;             // 0..2047
            int isB = idx >> 10;
            int e = idx & 1023;                  // 128 rows x 8 chunks
            int row = e >> 3, cc = e & 7;
            const __half* src = (isB ? gB : gA) + (size_t)row * KDIM + t * 64 + cc * 8;
            cpasync16(smem_u32((isB ? dB : dA) + row * SSTRIDE + cc * 8), src);
        }
        asm volatile("cp.async.commit_group;\n" ::: "memory");
    };

    float acc[4][4][4];
    #pragma unroll
    for (int i = 0; i < 4; ++i)
        #pragma unroll
        for (int j = 0; j < 4; ++j)
            #pragma unroll
            for (int e = 0; e < 4; ++e) acc[i][j][e] = 0.f;

    load_tile(0, 0);
    load_tile(1, 1);

    #pragma unroll 1
    for (int kt = 0; kt < 8; ++kt) {
        const int buf = kt % 3;
        if (kt < 7) asm volatile("cp.async.wait_group 1;\n" ::: "memory");
        else        asm volatile("cp.async.wait_group 0;\n" ::: "memory");
        __syncthreads();

        if (kt + 2 < 8) load_tile(kt + 2, (kt + 2) % 3);

        const __half* cA = sbase + buf * 2 * 128 * SSTRIDE;
        const __half* cB = cA + 128 * SSTRIDE;
        #pragma unroll
        for (int kk = 0; kk < 4; ++kk) {
            uint32_t af[4][4];
            #pragma unroll
            for (int mi = 0; mi < 4; ++mi) {
                int row = wm * 64 + mi * 16 + (lane & 15);
                int col = kk * 16 + ((lane >> 4) << 3);
                ldsm_x4(af[mi], &cA[row * SSTRIDE + col]);
            }
            uint32_t bf[2][4];
            #pragma unroll
            for (int nh = 0; nh < 2; ++nh) {
                int row = wn * 32 + nh * 16 + (lane & 7) + ((lane & 16) ? 8 : 0);
                int col = kk * 16 + ((lane & 8) ? 8 : 0);
                ldsm_x4(bf[nh], &cB[row * SSTRIDE + col]);
            }
            #pragma unroll
            for (int mi = 0; mi < 4; ++mi)
                #pragma unroll
                for (int ni = 0; ni < 4; ++ni)
                    mma16816(acc[mi][ni], af[mi], bf[ni >> 1][(ni & 1) * 2],
                             bf[ni >> 1][(ni & 1) * 2 + 1]);
        }
    }

    // epilogue
    const int g = lane >> 2, t = lane & 3;
    #pragma unroll
    for (int mi = 0; mi < 4; ++mi) {
        #pragma unroll
        for (int ni = 0; ni < 4; ++ni) {
            int col = bn * 128 + wn * 32 + ni * 8 + 2 * t;
            float bc0 = bias[col], bc1 = bias[col + 1];
            #pragma unroll
            for (int hh = 0; hh < 2; ++hh) {
                int row = bm * 128 + wm * 64 + mi * 16 + g + hh * 8;
                float v0 = acc[mi][ni][hh * 2 + 0] + bc0;
                float v1 = acc[mi][ni][hh * 2 + 1] + bc1;
                if (MODE == 0) {
                    int three = col >> 9, head = (col >> 5) & 15, d = col & 31;
                    if (three == 0) { v0 *= qscale; v1 *= qscale; }
                    size_t dst = ((((size_t)(row >> 6) * HEADS + head) * 3 + three) * WIN
                                  + (row & 63)) * DH + d;
                    *(__half2*)(g_qkv + dst) = __floats2half2_rn(v0, v1);
                } else {
                    *(float2*)(outf + (size_t)row * KDIM + col) = make_float2(v0, v1);
                }
            }
        }
    }
}

// ---------------- window attention: one CTA per (window, head) ----------------
__global__ __launch_bounds__(128) void attn_kernel(const float* __restrict__ table) {
    __shared__ __half sq[64 * 40], sk[64 * 40], sv[64 * 40];
    __shared__ float stab[225];

    const int bh = blockIdx.x;
    const int h = bh & (HEADS - 1);
    const int tid = threadIdx.x, lane = tid & 31, warp = tid >> 5;

    const __half* base = g_qkv + (size_t)bh * 3 * WIN * DH;
    for (int c = tid; c < 768; c += 128) {
        int mat = c >> 8, rc = c & 255, row = rc >> 2, cc = rc & 3;
        float4 v = *(const float4*)(base + mat * 2048 + row * 32 + cc * 8);
        __half* dst = (mat == 0) ? sq : (mat == 1) ? sk : sv;
        *(float4*)(dst + row * 40 + cc * 8) = v;
    }
    for (int i = tid; i < 225; i += 128) stab[i] = table[h * 225 + i];
    __syncthreads();

    const int r0 = warp * 16;
    float s[8][4];
    #pragma unroll
    for (int i = 0; i < 8; ++i)
        #pragma unroll
        for (int e = 0; e < 4; ++e) s[i][e] = 0.f;

    #pragma unroll
    for (int kk = 0; kk < 2; ++kk) {
        uint32_t a[4];
        {
            int row = r0 + (lane & 15);
            int col = kk * 16 + ((lane >> 4) << 3);
            ldsm_x4(a, &sq[row * 40 + col]);
        }
        #pragma unroll
        for (int nh = 0; nh < 4; ++nh) {
            uint32_t b[4];
            int row = nh * 16 + (lane & 7) + ((lane & 16) ? 8 : 0);
            int col = kk * 16 + ((lane & 8) ? 8 : 0);
            ldsm_x4(b, &sk[row * 40 + col]);
            mma16816(s[nh * 2],     a, b[0], b[1]);
            mma16816(s[nh * 2 + 1], a, b[2], b[3]);
        }
    }

    const int g = lane >> 2, t = lane & 3;
    const int i0 = r0 + g, i1 = r0 + 8 + g;
    const int ir0 = (i0 >> 3) + 7, ic0 = (i0 & 7) + 7;
    const int ir1 = (i1 >> 3) + 7, ic1 = (i1 & 7) + 7;

    float mx0 = -1e30f, mx1 = -1e30f;
    #pragma unroll
    for (int nt = 0; nt < 8; ++nt) {
        #pragma unroll
        for (int e = 0; e < 2; ++e) {
            int m = nt * 8 + 2 * t + e;
            int dr = m >> 3, dc = m & 7;
            s[nt][e]     += stab[(ir0 - dr) * 15 + (ic0 - dc)];
            s[nt][2 + e] += stab[(ir1 - dr) * 15 + (ic1 - dc)];
            mx0 = fmaxf(mx0, s[nt][e]);
            mx1 = fmaxf(mx1, s[nt][2 + e]);
        }
    }
    mx0 = fmaxf(mx0, __shfl_xor_sync(0xffffffffu, mx0, 1));
    mx0 = fmaxf(mx0, __shfl_xor_sync(0xffffffffu, mx0, 2));
    mx1 = fmaxf(mx1, __shfl_xor_sync(0xffffffffu, mx1, 1));
    mx1 = fmaxf(mx1, __shfl_xor_sync(0xffffffffu, mx1, 2));

    float sum0 = 0.f, sum1 = 0.f;
    #pragma unroll
    for (int nt = 0; nt < 8; ++nt) {
        #pragma unroll
        for (int e = 0; e < 2; ++e) {
            s[nt][e]     = __expf(s[nt][e] - mx0);     sum0 += s[nt][e];
            s[nt][2 + e] = __expf(s[nt][2 + e] - mx1); sum1 += s[nt][2 + e];
        }
    }
    sum0 += __shfl_xor_sync(0xffffffffu, sum0, 1);
    sum0 += __shfl_xor_sync(0xffffffffu, sum0, 2);
    sum1 += __shfl_xor_sync(0xffffffffu, sum1, 1);
    sum1 += __shfl_xor_sync(0xffffffffu, sum1, 2);
    const float inv0 = 1.f / sum0, inv1 = 1.f / sum1;
    #pragma unroll
    for (int nt = 0; nt < 8; ++nt) {
        s[nt][0] *= inv0; s[nt][1] *= inv0;
        s[nt][2] *= inv1; s[nt][3] *= inv1;
    }

    float o[4][4];
    #pragma unroll
    for (int i = 0; i < 4; ++i)
        #pragma unroll
        for (int e = 0; e < 4; ++e) o[i][e] = 0.f;

    #pragma unroll
    for (int kk = 0; kk < 4; ++kk) {
        uint32_t pa[4];
        pa[0] = packh2(s[2 * kk][0],     s[2 * kk][1]);
        pa[1] = packh2(s[2 * kk][2],     s[2 * kk][3]);
        pa[2] = packh2(s[2 * kk + 1][0], s[2 * kk + 1][1]);
        pa[3] = packh2(s[2 * kk + 1][2], s[2 * kk + 1][3]);
        #pragma unroll
        for (int nh = 0; nh < 2; ++nh) {
            uint32_t b[4];
            int row = kk * 16 + (lane & 7) + ((lane & 8) ? 8 : 0);
            int col = nh * 16 + ((lane & 16) ? 8 : 0);
            ldsm_x4_t(b, &sv[row * 40 + col]);
            mma16816(o[nh * 2],     pa, b[0], b[1]);
            mma16816(o[nh * 2 + 1], pa, b[2], b[3]);
        }
    }

    const int b_idx = bh >> 4;
    const size_t row0 = (size_t)b_idx * 64 + i0;
    const size_t row1 = (size_t)b_idx * 64 + i1;
    #pragma unroll
    for (int ni = 0; ni < 4; ++ni) {
        int col = h * 32 + ni * 8 + 2 * t;
        *(__half2*)(g_attnout + row0 * KDIM + col) = __floats2half2_rn(o[ni][0], o[ni][1]);
        *(__half2*)(g_attnout + row1 * KDIM + col) = __floats2half2_rn(o[ni][2], o[ni][3]);
    }
}

// ---------------- launch ----------------
extern "C" void kernel_launch(void* const* d_in, const int* in_sizes, int n_in,
                              void* d_out, int out_size) {
    const float* x     = (const float*)d_in[0];
    const float* wqkv  = (const float*)d_in[1];
    const float* bqkv  = (const float*)d_in[2];
    const float* tab   = (const float*)d_in[3];
    const float* wproj = (const float*)d_in[4];
    const float* bproj = (const float*)d_in[5];
    float* out = (float*)d_out;

    static int attr_set = 0;
    if (!attr_set) {
        cudaFuncSetAttribute(gemm_hmma_kernel<0>, cudaFuncAttributeMaxDynamicSharedMemorySize, GEMM_SMEM_BYTES);
        cudaFuncSetAttribute(gemm_hmma_kernel<1>, cudaFuncAttributeMaxDynamicSharedMemorySize, GEMM_SMEM_BYTES);
        attr_set = 1;
    }

    conv_x_kernel<<<65536, 256>>>(x);
    conv_w_kernel<<<3072, 256>>>(wqkv, wproj);
    gemm_hmma_kernel<0><<<dim3(NQKV / 128, MTOT / 128), 256, GEMM_SMEM_BYTES>>>(bqkv, nullptr);
    attn_kernel<<<NB * HEADS, 128>>>(tab);
    gemm_hmma_kernel<1><<<dim3(KDIM / 128, MTOT / 128), 256, GEMM_SMEM_BYTES>>>(bproj, out);
}